// round 15
// baseline (speedup 1.0000x reference)
#include <cuda_runtime.h>
#include <cuda_fp16.h>
#include <cstdint>

#define TOKENS 4096
#define DM 4096
#define DF 16384

// Scratch (device globals: allocation-free rule)
__device__ __half g_W1T[(size_t)DF * DM];    // W1^T: [DF][DM], fp16
__device__ __half g_W2T[(size_t)DM * DF];    // W2^T: [DM][DF], fp16
__device__ __half g_h[(size_t)TOKENS * DF];  // intermediate activations, fp16
__device__ __half g_xh[(size_t)TOKENS * DM]; // x, fp16

// ---------------- helpers ----------------
__device__ __forceinline__ uint32_t smem_u32(const void* p) {
    uint32_t a;
    asm("{ .reg .u64 t; cvta.to.shared.u64 t, %1; cvt.u32.u64 %0, t; }" : "=r"(a) : "l"(p));
    return a;
}
// SW64 swizzle for 64-byte rows
__device__ __forceinline__ uint32_t sw64(uint32_t off) { return off ^ ((off >> 3) & 0x30); }

__device__ __forceinline__ void cp16(uint32_t s, const void* g) {
    asm volatile("cp.async.cg.shared.global [%0], [%1], 16;" :: "r"(s), "l"(g));
}
#define CP_COMMIT() asm volatile("cp.async.commit_group;" ::: "memory")
#define CP_WAIT(n)  asm volatile("cp.async.wait_group %0;" :: "n"(n) : "memory")

#define LDSM4(r, addr) \
    asm volatile("ldmatrix.sync.aligned.m8n8.x4.shared.b16 {%0,%1,%2,%3}, [%4];" \
        : "=r"((r)[0]), "=r"((r)[1]), "=r"((r)[2]), "=r"((r)[3]) : "r"(addr))

__device__ __forceinline__ void mma16(float* c, const uint32_t* a, uint32_t b0, uint32_t b1) {
    asm volatile(
        "mma.sync.aligned.m16n8k16.row.col.f32.f16.f16.f32 "
        "{%0,%1,%2,%3}, {%4,%5,%6,%7}, {%8,%9}, {%0,%1,%2,%3};"
        : "+f"(c[0]), "+f"(c[1]), "+f"(c[2]), "+f"(c[3])
        : "r"(a[0]), "r"(a[1]), "r"(a[2]), "r"(a[3]), "r"(b0), "r"(b1));
}

__device__ __forceinline__ float gelu_tanh(float v) {
    float u = 0.7978845608028654f * (v + 0.044715f * v * v * v);
    float e = __expf(-2.0f * fabsf(u));
    float t = (1.0f - e) / (1.0f + e);
    t = copysignf(t, u);
    return 0.5f * v * (1.0f + t);
}

// ---------------- transpose + fp16 convert: src[R][C] -> dst[C][R] ----------------
__global__ void transpose_h(const float* __restrict__ src, __half* __restrict__ dst,
                            int R, int C) {
    __shared__ float tile[32][33];
    int c0 = blockIdx.x * 32, r0 = blockIdx.y * 32;
    int tx = threadIdx.x & 31, ty = threadIdx.x >> 5;  // 256 threads
#pragma unroll
    for (int i = 0; i < 32; i += 8)
        tile[ty + i][tx] = src[(size_t)(r0 + ty + i) * C + c0 + tx];
    __syncthreads();
#pragma unroll
    for (int i = 0; i < 32; i += 8)
        dst[(size_t)(c0 + ty + i) * R + r0 + tx] = __float2half_rn(tile[tx][ty + i]);
}

// ---------------- fp32 -> fp16 elementwise ----------------
__global__ void tohalf_k(const float* __restrict__ src, __half* __restrict__ dst, int n4) {
    int i = blockIdx.x * blockDim.x + threadIdx.x;
    if (i < n4) {
        float4 v = ((const float4*)src)[i];
        ((__half2*)dst)[i * 2 + 0] = __floats2half2_rn(v.x, v.y);
        ((__half2*)dst)[i * 2 + 1] = __floats2half2_rn(v.z, v.w);
    }
}

// ---------------- fp16 mma.sync GEMM (round-10 frontier config) ----------------
// C[M,N] = f(A[M,K] @ Bt[N,K]^T + bias); CTA tile 128x128, 8 warps (2x4),
// warp tile 64x32, NSTG=6 ring, 2 chunks per barrier, 2 CTAs/SM.
// MODE 0: GELU + fp16 out. MODE 1: +bias fp32 out.
constexpr int TM = 128, TN = 128, TK = 32, NSTG = 6;
constexpr int A_BYTES = TM * TK * 2;             // 8192
constexpr int B_BYTES = TN * TK * 2;             // 8192
constexpr int STAGE_BYTES = A_BYTES + B_BYTES;   // 16384
constexpr int SM_BIAS   = 0;                     // 128 floats
constexpr int SM_STAGES = 1024;
constexpr int SMEM_TOTAL = SM_STAGES + NSTG * STAGE_BYTES;  // 99328 -> 2 CTAs/SM

template <int MODE>
__global__ void __launch_bounds__(256, 2)
ffn_gemm(const __half* __restrict__ A, const __half* __restrict__ Bt,
         const float* __restrict__ bias, void* __restrict__ Cv,
         int M, int N, int K) {
    extern __shared__ char smem[];
    uint32_t sb = smem_u32(smem);
    int tid = threadIdx.x;
    int wid = tid >> 5, lid = tid & 31;
    int warp_m = wid & 1, warp_n = wid >> 1;   // 2 x 4 warp grid, warp tile 64x32

    // L2-friendly tile swizzle: groups of 8 N-tiles x all M-tiles
    int tiles_m = M / TM;
    const int GW = 8;
    int per_group = GW * tiles_m;
    int g = blockIdx.x / per_group;
    int r = blockIdx.x % per_group;
    int nt = g * GW + (r % GW);
    int mt = r / GW;
    int m0 = mt * TM, n0 = nt * TN;

    // bias tile -> smem
    float* bsm = (float*)(smem + SM_BIAS);
    if (tid < TN) bsm[tid] = bias[n0 + tid];

    // Precomputed per-thread cp.async offsets (loop-invariant; A and B share
    // the same 128-row x 64B pattern). 2 smem swizzled + 2 gmem element offsets.
    uint32_t soff0, soff1;
    int goff0, goff1;
    {
        int e0 = tid, e1 = tid + 256;
        soff0 = sw64((uint32_t)(e0 >> 2) * 64 + (e0 & 3) * 16);
        soff1 = sw64((uint32_t)(e1 >> 2) * 64 + (e1 & 3) * 16);
        goff0 = (e0 >> 2) * K + (e0 & 3) * 8;
        goff1 = (e1 >> 2) * K + (e1 & 3) * 8;
    }

    // ldmatrix per-lane SWIZZLED base offsets (XOR trick: the k16 step adds
    // 32 bytes = bit 5, below the SW64 mask inputs, so sw64(off+32)==sw64(off)^32)
    uint32_t aswz[4], bswz[2];
    {
        int l = lid;
        int matA = l >> 3, rA = l & 7;
        int rowA = (matA & 1) * 8 + rA;
        int colA = (matA >> 1) * 16;
#pragma unroll
        for (int mf = 0; mf < 4; mf++)
            aswz[mf] = sw64((uint32_t)(warp_m * 64 + mf * 16 + rowA) * 64 + colA);
        int nB = ((l >> 4) & 1) * 8 + (l & 7);
        int colB = ((l >> 3) & 1) * 16;
#pragma unroll
        for (int np = 0; np < 2; np++)
            bswz[np] = sw64((uint32_t)(warp_n * 32 + np * 16 + nB) * 64 + colB);
    }

    float acc[4][4][4];
#pragma unroll
    for (int i = 0; i < 4; i++)
#pragma unroll
        for (int j = 0; j < 4; j++)
#pragma unroll
            for (int k = 0; k < 4; k++) acc[i][j][k] = 0.0f;

    int nch = K / TK;   // 128 or 512, even

    const __half* Abase = A + (size_t)m0 * K;
    const __half* Bbase = Bt + (size_t)n0 * K;

    auto load_stage = [&](int stage, int ch) {
        uint32_t abase = sb + SM_STAGES + stage * STAGE_BYTES;
        uint32_t bbase = abase + A_BYTES;
        const __half* Ap = Abase + ch * TK;
        const __half* Bp = Bbase + ch * TK;
        cp16(abase + soff0, Ap + goff0);
        cp16(abase + soff1, Ap + goff1);
        cp16(bbase + soff0, Bp + goff0);
        cp16(bbase + soff1, Bp + goff1);
    };

    // one k16 micro-step: 6 batched LDSM + 16 MMAs (ptxas schedules the batch)
    auto kstep = [&](uint32_t ab, uint32_t bb, uint32_t ksoff) {
        uint32_t Af[4][4], Bf[2][4];
#pragma unroll
        for (int mf = 0; mf < 4; mf++)
            LDSM4(Af[mf], ab + (aswz[mf] ^ ksoff));
#pragma unroll
        for (int np = 0; np < 2; np++)
            LDSM4(Bf[np], bb + (bswz[np] ^ ksoff));
#pragma unroll
        for (int mf = 0; mf < 4; mf++)
#pragma unroll
            for (int nf = 0; nf < 4; nf++)
                mma16(acc[mf][nf], Af[mf],
                      Bf[nf >> 1][(nf & 1) * 2], Bf[nf >> 1][(nf & 1) * 2 + 1]);
    };

    // prologue: chunks 0..3 into stages 0..3 (ring of 6)
    for (int s = 0; s < 4; s++) { load_stage(s, s); CP_COMMIT(); }

    // main loop: 2 chunks per barrier
    for (int ch = 0; ch < nch; ch += 2) {
        CP_WAIT(2);           // chunks ch, ch+1 resident; ch+2, ch+3 in flight
        __syncthreads();

        uint32_t ab0 = sb + SM_STAGES + (ch % NSTG) * STAGE_BYTES;
        uint32_t ab1 = sb + SM_STAGES + ((ch + 1) % NSTG) * STAGE_BYTES;

        kstep(ab0, ab0 + A_BYTES, 0);      // MMAs flowing first

        int pf = ch + 4;                   // stage (ch+4)%6: no read overlap
        if (pf < nch) load_stage(pf % NSTG, pf);
        CP_COMMIT();

        kstep(ab0, ab0 + A_BYTES, 32);

        pf = ch + 5;                       // stage (ch+5)%6: no read overlap
        if (pf < nch) load_stage(pf % NSTG, pf);
        CP_COMMIT();

        kstep(ab1, ab1 + A_BYTES, 0);
        kstep(ab1, ab1 + A_BYTES, 32);
    }
    __syncthreads();

    // epilogue: bias (+ GELU/fp16 for MODE 0; fp32 for MODE 1)
    int gq = lid >> 2, t4 = lid & 3;
#pragma unroll
    for (int mf = 0; mf < 4; mf++) {
#pragma unroll
        for (int nf = 0; nf < 4; nf++) {
            int ccol = warp_n * 32 + nf * 8 + t4 * 2;
            float bv0 = bsm[ccol], bv1 = bsm[ccol + 1];
            int grow = m0 + warp_m * 64 + mf * 16 + gq;
            int gcol = n0 + ccol;
#pragma unroll
            for (int h = 0; h < 2; h++) {  // h=0: row g, h=1: row g+8
                float v0 = acc[mf][nf][h * 2 + 0] + bv0;
                float v1 = acc[mf][nf][h * 2 + 1] + bv1;
                if (MODE == 0) {
                    __half2 o = __floats2half2_rn(gelu_tanh(v0), gelu_tanh(v1));
                    *(__half2*)((__half*)Cv + (size_t)(grow + h * 8) * N + gcol) = o;
                } else {
                    float2 o = make_float2(v0, v1);
                    *(float2*)((float*)Cv + (size_t)(grow + h * 8) * N + gcol) = o;
                }
            }
        }
    }
}

// ---------------- launch ----------------
extern "C" void kernel_launch(void* const* d_in, const int* in_sizes, int n_in,
                              void* d_out, int out_size) {
    const float* x  = (const float*)d_in[0];
    const float* W1 = (const float*)d_in[1];
    const float* b1 = (const float*)d_in[2];
    const float* W2 = (const float*)d_in[3];
    const float* b2 = (const float*)d_in[4];
    float* y = (float*)d_out;

    __half *w1t, *w2t, *h, *xh;
    cudaGetSymbolAddress((void**)&w1t, g_W1T);
    cudaGetSymbolAddress((void**)&w2t, g_W2T);
    cudaGetSymbolAddress((void**)&h,   g_h);
    cudaGetSymbolAddress((void**)&xh,  g_xh);

    cudaFuncSetAttribute(ffn_gemm<0>, cudaFuncAttributeMaxDynamicSharedMemorySize, SMEM_TOTAL);
    cudaFuncSetAttribute(ffn_gemm<1>, cudaFuncAttributeMaxDynamicSharedMemorySize, SMEM_TOTAL);

    // W1 [DM,DF] -> W1T [DF,DM];  W2 [DF,DM] -> W2T [DM,DF]  (fp16)
    transpose_h<<<dim3(DF / 32, DM / 32), 256>>>(W1, w1t, DM, DF);
    transpose_h<<<dim3(DM / 32, DF / 32), 256>>>(W2, w2t, DF, DM);
    // x -> fp16
    {
        int n4 = TOKENS * DM / 4;
        tohalf_k<<<(n4 + 255) / 256, 256>>>(x, xh, n4);
    }

    // h = fp16(gelu(x @ W1 + b1)); grid 4096 CTAs
    ffn_gemm<0><<<(DF / TN) * (TOKENS / TM), 256, SMEM_TOTAL>>>(
        xh, w1t, b1, h, TOKENS, DF, DM);
    // y = h @ W2 + b2; grid 1024 CTAs
    ffn_gemm<1><<<(DM / TN) * (TOKENS / TM), 256, SMEM_TOTAL>>>(
        h, w2t, b2, y, TOKENS, DM, DF);
}

// round 16
// speedup vs baseline: 1.1066x; 1.1066x over previous
#include <cuda_runtime.h>
#include <cuda_fp16.h>
#include <cstdint>

#define TOKENS 4096
#define DM 4096
#define DF 16384

// Scratch (device globals: allocation-free rule)
__device__ __half g_W1T[(size_t)DF * DM];    // W1^T: [DF][DM], fp16
__device__ __half g_W2T[(size_t)DM * DF];    // W2^T: [DM][DF], fp16
__device__ __half g_h[(size_t)TOKENS * DF];  // intermediate activations, fp16
__device__ __half g_xh[(size_t)TOKENS * DM]; // x, fp16

// ---------------- helpers ----------------
__device__ __forceinline__ uint32_t smem_u32(const void* p) {
    uint32_t a;
    asm("{ .reg .u64 t; cvta.to.shared.u64 t, %1; cvt.u32.u64 %0, t; }" : "=r"(a) : "l"(p));
    return a;
}
// SW64 swizzle for 64-byte rows
__device__ __forceinline__ uint32_t sw64(uint32_t off) { return off ^ ((off >> 3) & 0x30); }

__device__ __forceinline__ void cp16(uint32_t s, const void* g) {
    asm volatile("cp.async.cg.shared.global [%0], [%1], 16;" :: "r"(s), "l"(g));
}
#define CP_COMMIT() asm volatile("cp.async.commit_group;" ::: "memory")
#define CP_WAIT(n)  asm volatile("cp.async.wait_group %0;" :: "n"(n) : "memory")

#define LDSM4(r, addr) \
    asm volatile("ldmatrix.sync.aligned.m8n8.x4.shared.b16 {%0,%1,%2,%3}, [%4];" \
        : "=r"((r)[0]), "=r"((r)[1]), "=r"((r)[2]), "=r"((r)[3]) : "r"(addr))

__device__ __forceinline__ void mma16(float* c, const uint32_t* a, uint32_t b0, uint32_t b1) {
    asm volatile(
        "mma.sync.aligned.m16n8k16.row.col.f32.f16.f16.f32 "
        "{%0,%1,%2,%3}, {%4,%5,%6,%7}, {%8,%9}, {%0,%1,%2,%3};"
        : "+f"(c[0]), "+f"(c[1]), "+f"(c[2]), "+f"(c[3])
        : "r"(a[0]), "r"(a[1]), "r"(a[2]), "r"(a[3]), "r"(b0), "r"(b1));
}

__device__ __forceinline__ float gelu_tanh(float v) {
    float u = 0.7978845608028654f * (v + 0.044715f * v * v * v);
    float e = __expf(-2.0f * fabsf(u));
    float t = (1.0f - e) / (1.0f + e);
    t = copysignf(t, u);
    return 0.5f * v * (1.0f + t);
}

// ---------------- transpose + fp16 convert, wide stores ----------------
// src[R][C] fp32 -> dst[C][R] fp16. 64 src-rows x 32 src-cols per block;
// each thread writes __half2 -> 128B per warp store (full lines).
__global__ void transpose_h2(const float* __restrict__ src, __half* __restrict__ dst,
                             int R, int C) {
    __shared__ float tile[64][33];
    int c0 = blockIdx.x * 32, r0 = blockIdx.y * 64;
    int tx = threadIdx.x & 31, ty = threadIdx.x >> 5;  // 256 threads: ty 0..7
#pragma unroll
    for (int i = 0; i < 64; i += 8)
        tile[ty + i][tx] = src[(size_t)(r0 + ty + i) * C + c0 + tx];
    __syncthreads();
#pragma unroll
    for (int i = 0; i < 32; i += 8) {
        int cc = ty + i;
        __half2 v = __floats2half2_rn(tile[2 * tx][cc], tile[2 * tx + 1][cc]);
        *(__half2*)(dst + (size_t)(c0 + cc) * R + r0 + 2 * tx) = v;
    }
}

// ---------------- fp32 -> fp16 elementwise ----------------
__global__ void tohalf_k(const float* __restrict__ src, __half* __restrict__ dst, int n4) {
    int i = blockIdx.x * blockDim.x + threadIdx.x;
    if (i < n4) {
        float4 v = ((const float4*)src)[i];
        ((__half2*)dst)[i * 2 + 0] = __floats2half2_rn(v.x, v.y);
        ((__half2*)dst)[i * 2 + 1] = __floats2half2_rn(v.z, v.w);
    }
}

// ---------------- fp16 mma.sync GEMM (exact round-10 core; frozen) ----------------
// C[M,N] = act(A[M,K] @ Bt[N,K]^T + bias); A, Bt fp16 K-major row-major.
constexpr int TM = 128, TN = 128, TK = 32, NSTG = 6;
constexpr int A_BYTES = TM * TK * 2;             // 8192
constexpr int B_BYTES = TN * TK * 2;             // 8192
constexpr int STAGE_BYTES = A_BYTES + B_BYTES;   // 16384
constexpr int SM_BIAS   = 0;                     // 128 floats
constexpr int SM_STAGES = 1024;
constexpr int SMEM_TOTAL = SM_STAGES + NSTG * STAGE_BYTES;  // 99328 -> 2 CTAs/SM

template <bool GELU_HALF_OUT>
__global__ void __launch_bounds__(256, 2)
ffn_gemm(const __half* __restrict__ A, const __half* __restrict__ Bt,
         const float* __restrict__ bias, void* __restrict__ Cv,
         int M, int N, int K) {
    extern __shared__ char smem[];
    uint32_t sb = smem_u32(smem);
    int tid = threadIdx.x;
    int wid = tid >> 5, lid = tid & 31;
    int warp_m = wid & 1, warp_n = wid >> 1;   // 2 x 4 warp grid, warp tile 64x32

    // L2-friendly tile swizzle: groups of 8 N-tiles x all M-tiles
    int tiles_m = M / TM;
    const int GW = 8;
    int per_group = GW * tiles_m;
    int g = blockIdx.x / per_group;
    int r = blockIdx.x % per_group;
    int nt = g * GW + (r % GW);
    int mt = r / GW;
    int m0 = mt * TM, n0 = nt * TN;

    // bias tile -> smem
    float* bsm = (float*)(smem + SM_BIAS);
    if (tid < TN) bsm[tid] = bias[n0 + tid];

    // ldmatrix per-lane SWIZZLED base offsets (XOR trick: the k16 step adds
    // 32 bytes = bit 5, below the SW64 mask inputs, so sw64(off+32)==sw64(off)^32)
    uint32_t aswz[4], bswz[2];
    {
        int l = lid;
        int matA = l >> 3, rA = l & 7;
        int rowA = (matA & 1) * 8 + rA;
        int colA = (matA >> 1) * 16;
#pragma unroll
        for (int mf = 0; mf < 4; mf++)
            aswz[mf] = sw64((uint32_t)(warp_m * 64 + mf * 16 + rowA) * 64 + colA);
        int nB = ((l >> 4) & 1) * 8 + (l & 7);
        int colB = ((l >> 3) & 1) * 16;
#pragma unroll
        for (int np = 0; np < 2; np++)
            bswz[np] = sw64((uint32_t)(warp_n * 32 + np * 16 + nB) * 64 + colB);
    }

    float acc[4][4][4];
#pragma unroll
    for (int i = 0; i < 4; i++)
#pragma unroll
        for (int j = 0; j < 4; j++)
#pragma unroll
            for (int k = 0; k < 4; k++) acc[i][j][k] = 0.0f;

    int nch = K / TK;   // even for all our K

    auto load_stage = [&](int stage, int ch) {
        uint32_t abase = sb + SM_STAGES + stage * STAGE_BYTES;
        uint32_t bbase = abase + A_BYTES;
        const __half* Ap = A + (size_t)m0 * K + ch * TK;
        const __half* Bp = Bt + (size_t)n0 * K + ch * TK;
#pragma unroll
        for (int j = 0; j < 2; j++) {  // A: 512 x 16B
            int e = tid + j * 256;
            int row = e >> 2, c = e & 3;
            cp16(abase + sw64(row * 64 + c * 16), Ap + (size_t)row * K + c * 8);
        }
#pragma unroll
        for (int j = 0; j < 2; j++) {  // B: 512 x 16B
            int e = tid + j * 256;
            int row = e >> 2, c = e & 3;
            cp16(bbase + sw64(row * 64 + c * 16), Bp + (size_t)row * K + c * 8);
        }
    };

    // one k16 micro-step: 6 batched LDSM + 16 MMAs (ks is compile-time 0 or 1)
    auto kstep = [&](uint32_t ab, uint32_t bb, uint32_t ksoff) {
        uint32_t Af[4][4], Bf[2][4];
#pragma unroll
        for (int mf = 0; mf < 4; mf++)
            LDSM4(Af[mf], ab + (aswz[mf] ^ ksoff));
#pragma unroll
        for (int np = 0; np < 2; np++)
            LDSM4(Bf[np], bb + (bswz[np] ^ ksoff));
#pragma unroll
        for (int mf = 0; mf < 4; mf++)
#pragma unroll
            for (int nf = 0; nf < 4; nf++)
                mma16(acc[mf][nf], Af[mf],
                      Bf[nf >> 1][(nf & 1) * 2], Bf[nf >> 1][(nf & 1) * 2 + 1]);
    };

    // prologue: chunks 0..3 into stages 0..3 (ring has 6 slots)
    for (int s = 0; s < 4; s++) { load_stage(s, s); CP_COMMIT(); }

    // main loop: 2 chunks per barrier
    for (int ch = 0; ch < nch; ch += 2) {
        CP_WAIT(2);           // chunks ch, ch+1 resident; ch+2, ch+3 in flight
        __syncthreads();

        uint32_t ab0 = sb + SM_STAGES + (ch % NSTG) * STAGE_BYTES;
        uint32_t ab1 = sb + SM_STAGES + ((ch + 1) % NSTG) * STAGE_BYTES;

        kstep(ab0, ab0 + A_BYTES, 0);      // MMAs flowing first

        int pf = ch + 4;                   // -> stage (ch+4)%6, no read overlap
        if (pf < nch) load_stage(pf % NSTG, pf);
        CP_COMMIT();

        kstep(ab0, ab0 + A_BYTES, 32);

        pf = ch + 5;                       // -> stage (ch+5)%6, no read overlap
        if (pf < nch) load_stage(pf % NSTG, pf);
        CP_COMMIT();

        kstep(ab1, ab1 + A_BYTES, 0);
        kstep(ab1, ab1 + A_BYTES, 32);
    }
    __syncthreads();

    // epilogue: bias (+ GELU, fp16 out for layer 1; fp32 out for layer 2)
    int gq = lid >> 2, t4 = lid & 3;
#pragma unroll
    for (int mf = 0; mf < 4; mf++) {
#pragma unroll
        for (int nf = 0; nf < 4; nf++) {
            int ccol = warp_n * 32 + nf * 8 + t4 * 2;
            float bv0 = bsm[ccol], bv1 = bsm[ccol + 1];
            int grow = m0 + warp_m * 64 + mf * 16 + gq;
            int gcol = n0 + ccol;
#pragma unroll
            for (int h = 0; h < 2; h++) {  // h=0: row g, h=1: row g+8
                float v0 = acc[mf][nf][h * 2 + 0] + bv0;
                float v1 = acc[mf][nf][h * 2 + 1] + bv1;
                if (GELU_HALF_OUT) {
                    __half2 o = __floats2half2_rn(gelu_tanh(v0), gelu_tanh(v1));
                    *(__half2*)((__half*)Cv + (size_t)(grow + h * 8) * N + gcol) = o;
                } else {
                    float2 o = make_float2(v0, v1);
                    *(float2*)((float*)Cv + (size_t)(grow + h * 8) * N + gcol) = o;
                }
            }
        }
    }
}

// ---------------- launch ----------------
extern "C" void kernel_launch(void* const* d_in, const int* in_sizes, int n_in,
                              void* d_out, int out_size) {
    const float* x  = (const float*)d_in[0];
    const float* W1 = (const float*)d_in[1];
    const float* b1 = (const float*)d_in[2];
    const float* W2 = (const float*)d_in[3];
    const float* b2 = (const float*)d_in[4];
    float* y = (float*)d_out;

    __half *w1t, *w2t, *h, *xh;
    cudaGetSymbolAddress((void**)&w1t, g_W1T);
    cudaGetSymbolAddress((void**)&w2t, g_W2T);
    cudaGetSymbolAddress((void**)&h,   g_h);
    cudaGetSymbolAddress((void**)&xh,  g_xh);

    cudaFuncSetAttribute(ffn_gemm<true>,  cudaFuncAttributeMaxDynamicSharedMemorySize, SMEM_TOTAL);
    cudaFuncSetAttribute(ffn_gemm<false>, cudaFuncAttributeMaxDynamicSharedMemorySize, SMEM_TOTAL);

    // W1 [DM,DF] -> W1T [DF,DM];  W2 [DF,DM] -> W2T [DM,DF]  (fp16, wide stores)
    transpose_h2<<<dim3(DF / 32, DM / 64), 256>>>(W1, w1t, DM, DF);
    transpose_h2<<<dim3(DM / 32, DF / 64), 256>>>(W2, w2t, DF, DM);
    // x -> fp16
    {
        int n4 = TOKENS * DM / 4;
        tohalf_k<<<(n4 + 255) / 256, 256>>>(x, xh, n4);
    }

    // h = fp16(gelu(x @ W1 + b1)); grid 4096 CTAs
    ffn_gemm<true><<<(DF / TN) * (TOKENS / TM), 256, SMEM_TOTAL>>>(
        xh, w1t, b1, h, TOKENS, DF, DM);
    // y = h @ W2 + b2; grid 1024 CTAs
    ffn_gemm<false><<<(DM / TN) * (TOKENS / TM), 256, SMEM_TOTAL>>>(
        h, w2t, b2, y, TOKENS, DM, DF);
}